// round 4
// baseline (speedup 1.0000x reference)
#include <cuda_runtime.h>
#include <cooperative_groups.h>

namespace cg = cooperative_groups;

// Problem shapes
#define NB 512   // batch
#define NT 512   // time steps
#define NI 128   // input dim
#define NH 256   // hidden dim
#define NC 128   // output classes

// 64 clusters x 2 CTAs (128 CTAs on 148 SMs). Cluster owns 8 batch rows;
// CTA rank r owns hidden columns [r*128, r*128+128).
// 384 threads = 3 k-groups of 128 threads:
//   group 0: k in [0,128)   = X part        (reads x buffer)
//   group 1: k in [128,256) = h[0:128)      (reads h buffer)
//   group 2: k in [256,384) = h[128:256)    (reads h buffer)
// Each group thread computes partial pre-activations for 2 cols x 4 rows and
// stores them to smem. After one __syncthreads:
//   threads 0..255  : reduce 3 partials + bias, tanh, publish h_new into own
//                     AND peer (DSMEM) next-h buffer (ping-pong).
//   threads 256..383: stage X(t+1) into the x buffer (single-buffered: its
//                     readers finished before the barrier).
// One cluster.sync per step publishes h across the CTA pair.
// The final projection (H @ W_hq + b_q) is fused at the end: H lives in smem.
constexpr int ROWS    = 8;
constexpr int CPC     = 128;          // columns per CTA
constexpr int THREADS = 384;
constexpr int KTOT    = NI + NH;      // 384
constexpr int KG      = 128;          // k per group
constexpr int NGRP    = 3;

constexpr int WS_ELEMS  = KTOT * CPC;     // 49152 floats (192 KB)
constexpr int X_ELEMS   = NI * ROWS;      // 1024
constexpr int H_ELEMS   = NH * ROWS;      // 2048
constexpr int PRE_ELEMS = CPC * ROWS;     // 1024 per group

constexpr int OFF_X   = WS_ELEMS;
constexpr int OFF_H0  = OFF_X + X_ELEMS;
constexpr int OFF_H1  = OFF_H0 + H_ELEMS;
constexpr int OFF_PRE = OFF_H1 + H_ELEMS;
constexpr size_t SMEM_BYTES = (size_t)(OFF_PRE + NGRP * PRE_ELEMS) * sizeof(float);
// = 229376 B <= 232448 B (227 KB) limit

typedef unsigned long long u64;

__device__ __forceinline__ u64 pack2(float a, float b) {
    u64 r; asm("mov.b64 %0, {%1, %2};" : "=l"(r) : "f"(a), "f"(b)); return r;
}
// packed dual fma: d = a*b + d (two independent fp32 lanes)
__device__ __forceinline__ void fma2(u64& d, u64 a, u64 b) {
    asm("fma.rn.f32x2 %0, %1, %2, %0;" : "+l"(d) : "l"(a), "l"(b));
}

__global__ void __launch_bounds__(THREADS, 1) __cluster_dims__(2, 1, 1)
rnn_fused_kernel(const float* __restrict__ X,
                 const float* __restrict__ Wxh,
                 const float* __restrict__ Whh,
                 const float* __restrict__ bh,
                 const float* __restrict__ Whq,
                 const float* __restrict__ bq,
                 float* __restrict__ out)
{
    extern __shared__ float sm[];
    float* Ws   = sm;              // [KTOT][CPC]  combined weights, [k][j]
    float* xbuf = sm + OFF_X;      // [NI][ROWS]   x transposed
    float* hA   = sm + OFF_H0;     // [NH][ROWS]   h ping
    float* hB   = sm + OFF_H1;     // [NH][ROWS]   h pong
    float* pre  = sm + OFF_PRE;    // [NGRP][CPC][ROWS] partials

    cg::cluster_group cl = cg::this_cluster();
    const int rank  = (int)cl.block_rank();
    const int cid   = blockIdx.x >> 1;
    const int tid   = threadIdx.x;
    const int cb    = rank * CPC;
    const int bbase = cid * ROWS;
    const size_t RSTRIDE = (size_t)NT * NI;

    // ---- stage weights: Ws[k][j] = (k<NI ? Wxh : Whh)[k][cb+j], coalesced ----
    for (int idx = tid; idx < WS_ELEMS; idx += THREADS) {
        int k = idx >> 7, j = idx & 127;
        Ws[idx] = (k < NI) ? Wxh[(size_t)k * NH + cb + j]
                           : Whh[(size_t)(k - NI) * NH + cb + j];
    }
    // zero initial h
    for (int idx = tid; idx < H_ELEMS; idx += THREADS) hA[idx] = 0.0f;

    // ---- roles ----
    const int g   = tid >> 7;          // k-group 0..2
    const int gi  = tid & 127;
    const int j0  = 2 * (gi & 63);     // first of 2 columns (within CTA)
    const int ro  = 4 * (gi >> 6);     // first of 4 rows

    // finalize role (tid < 256)
    const int fjc = tid >> 1;          // column 0..127
    const int fro = 4 * (tid & 1);     // row offset 0 or 4
    float bias = 0.0f;
    if (tid < 256) bias = bh[cb + fjc];

    // x-stage role (tid >= 256): feature si, all 8 rows
    const int si = tid - 256;
    const float* Xs = X + (size_t)bbase * RSTRIDE + si;
    float xr[ROWS];
    if (tid >= 256) {
        // load x(0), stage it, then prefetch x(1)
        #pragma unroll
        for (int r = 0; r < ROWS; r++) xr[r] = Xs[(size_t)r * RSTRIDE];
        *(float4*)(xbuf + si * ROWS)     = make_float4(xr[0], xr[1], xr[2], xr[3]);
        *(float4*)(xbuf + si * ROWS + 4) = make_float4(xr[4], xr[5], xr[6], xr[7]);
        #pragma unroll
        for (int r = 0; r < ROWS; r++) xr[r] = Xs[(size_t)r * RSTRIDE + NI];
    }

    float* hcur = hA;
    float* hnxt = hB;
    float* pA = cl.map_shared_rank(hA, rank ^ 1);
    float* pB = cl.map_shared_rank(hB, rank ^ 1);
    float* pnxt = pB;

    const float* wp  = Ws + g * KG * CPC + j0;
    float*       prg = pre + g * PRE_ELEMS;

    __syncthreads();
    cl.sync();

    for (int t = 0; t < NT; t++) {
        // ---- main: partial pre-activation, 2 cols x 4 rows, k over group range ----
        const float* ap = ((g == 0) ? xbuf : (hcur + (g - 1) * KG * ROWS)) + ro;

        u64 a00 = 0ull, a01 = 0ull, a10 = 0ull, a11 = 0ull;
        #pragma unroll 8
        for (int k = 0; k < KG; k++) {
            float2 w = *(const float2*)(wp + k * CPC);
            u64 w0 = pack2(w.x, w.x);
            u64 w1 = pack2(w.y, w.y);
            ulonglong2 av = *(const ulonglong2*)(ap + k * ROWS);
            fma2(a00, w0, av.x); fma2(a01, w0, av.y);
            fma2(a10, w1, av.x); fma2(a11, w1, av.y);
        }
        // store partials: pre[g][col][rows]
        {
            ulonglong2 s0; s0.x = a00; s0.y = a01;
            ulonglong2 s1; s1.x = a10; s1.y = a11;
            *(ulonglong2*)(prg + j0 * ROWS + ro)       = s0;
            *(ulonglong2*)(prg + (j0 + 1) * ROWS + ro) = s1;
        }
        __syncthreads();

        if (tid < 256) {
            // ---- finalize: sum 3 partials + bias, tanh, publish own + peer ----
            const int off = fjc * ROWS + fro;
            float4 p0 = *(const float4*)(pre + off);
            float4 p1 = *(const float4*)(pre + PRE_ELEMS + off);
            float4 p2 = *(const float4*)(pre + 2 * PRE_ELEMS + off);
            float4 s;
            s.x = tanhf(p0.x + p1.x + p2.x + bias);
            s.y = tanhf(p0.y + p1.y + p2.y + bias);
            s.z = tanhf(p0.z + p1.z + p2.z + bias);
            s.w = tanhf(p0.w + p1.w + p2.w + bias);
            const int hoff = (cb + fjc) * ROWS + fro;
            *(float4*)(hnxt + hoff) = s;
            *(float4*)(pnxt + hoff) = s;
        } else {
            // ---- stage x(t+1), prefetch x(t+2) ----
            if (t + 1 < NT) {
                *(float4*)(xbuf + si * ROWS)     = make_float4(xr[0], xr[1], xr[2], xr[3]);
                *(float4*)(xbuf + si * ROWS + 4) = make_float4(xr[4], xr[5], xr[6], xr[7]);
            }
            if (t + 2 < NT) {
                const float* Xn = Xs + (size_t)(t + 2) * NI;
                #pragma unroll
                for (int r = 0; r < ROWS; r++) xr[r] = Xn[(size_t)r * RSTRIDE];
            }
        }

        cl.sync();   // h published in both CTAs; everyone done with hcur & xbuf

        float* tmp = hcur; hcur = hnxt; hnxt = tmp;
        pnxt = (hnxt == hA) ? pA : pB;
    }

    // ---- fused projection: out[8 rows][NC], rank splits columns 64/64 ----
    // hcur holds final H for all 256 hidden dims (own + peer halves).
    if (tid < 256) {
        const int c  = tid & 63;          // local out column
        const int rp = tid >> 6;          // row pair 0..3
        const int gc = rank * 64 + c;     // global out column

        float acc0 = 0.0f, acc1 = 0.0f;
        const float* wq = Whq + gc;
        #pragma unroll 8
        for (int k = 0; k < NH; k++) {
            float2 hh = *(const float2*)(hcur + k * ROWS + 2 * rp);
            float  wv = wq[(size_t)k * NC];
            acc0 = fmaf(hh.x, wv, acc0);
            acc1 = fmaf(hh.y, wv, acc1);
        }
        const float bqv = bq[gc];
        const int r0 = bbase + 2 * rp;
        out[(size_t)r0 * NC + gc]       = acc0 + bqv;
        out[(size_t)(r0 + 1) * NC + gc] = acc1 + bqv;
    }
}

extern "C" void kernel_launch(void* const* d_in, const int* in_sizes, int n_in,
                              void* d_out, int out_size)
{
    const float* X   = (const float*)d_in[0];
    const float* Wxh = (const float*)d_in[1];
    const float* Whh = (const float*)d_in[2];
    const float* bh  = (const float*)d_in[3];
    const float* Whq = (const float*)d_in[4];
    const float* bq  = (const float*)d_in[5];
    float* out = (float*)d_out;

    cudaFuncSetAttribute(rnn_fused_kernel,
                         cudaFuncAttributeMaxDynamicSharedMemorySize,
                         (int)SMEM_BYTES);

    rnn_fused_kernel<<<(NB / ROWS) * 2, THREADS, SMEM_BYTES>>>(
        X, Wxh, Whh, bh, Whq, bq, out);
}

// round 5
// speedup vs baseline: 1.1859x; 1.1859x over previous
#include <cuda_runtime.h>
#include <cooperative_groups.h>

namespace cg = cooperative_groups;

// Problem shapes
#define NB 512
#define NT 512
#define NI 128
#define NH 256
#define NC 128

typedef unsigned long long u64;

// ---------------------------------------------------------------------------
// Precomputed input projection U = X@Wxh + bh, laid out for the recurrence:
//   U[t][cid][rank][col(128)][row(8)]   (cid = batch-cluster 0..63, rank 0/1)
// 512*64*2*128*8 floats = 256 MB (static device scratch).
// ---------------------------------------------------------------------------
__device__ float g_U[(size_t)NT * 64 * 2 * 128 * 8];

__device__ __forceinline__ u64 pack2(float a, float b) {
    u64 r; asm("mov.b64 %0, {%1, %2};" : "=l"(r) : "f"(a), "f"(b)); return r;
}
__device__ __forceinline__ void unpack2(u64 v, float& a, float& b) {
    asm("mov.b64 {%0, %1}, %2;" : "=f"(a), "=f"(b) : "l"(v));
}
__device__ __forceinline__ void fma2(u64& d, u64 a, u64 b) {
    asm("fma.rn.f32x2 %0, %1, %2, %0;" : "+l"(d) : "l"(a), "l"(b));
}
__device__ __forceinline__ void fadd2(u64& d, u64 a) {
    asm("add.rn.f32x2 %0, %0, %1;" : "+l"(d) : "l"(a));
}
__device__ __forceinline__ void cp16(uint32_t dst, const void* src) {
    asm volatile("cp.async.cg.shared.global [%0], [%1], 16;" :: "r"(dst), "l"(src));
}
__device__ __forceinline__ void cp_commit() {
    asm volatile("cp.async.commit_group;");
}
__device__ __forceinline__ void cp_wait0() {
    asm volatile("cp.async.wait_group 0;" ::: "memory");
}

// ===========================================================================
// Kernel 1: precompute U = X@Wxh + bh.
// grid 1024 = 64 cid x 16 t-groups; block 256 threads; 4 t-tiles per iter.
// Thread = one output column c (0..255); per tile 8 rows accumulated in regs.
// ===========================================================================
constexpr int PC_THREADS = 256;
constexpr int PC_Q       = 4;                 // tiles (t values) per iteration
constexpr int PC_TG      = 32;                // t per block
constexpr size_t PC_SMEM = (size_t)(NI * NH + PC_Q * NI * 8) * 4; // 147456 B

__global__ void __launch_bounds__(PC_THREADS, 1)
precompute_kernel(const float* __restrict__ X,
                  const float* __restrict__ Wxh,
                  const float* __restrict__ bh)
{
    extern __shared__ float smp[];
    float* Wsp = smp;             // [k][c] = same layout as Wxh, 128 KB
    float* xT  = smp + NI * NH;   // [q][k][8]

    const int cid = blockIdx.x >> 4;
    const int tg  = blockIdx.x & 15;
    const int tid = threadIdx.x;

    for (int i = tid; i < NI * NH / 4; i += PC_THREADS)
        ((float4*)Wsp)[i] = ((const float4*)Wxh)[i];

    const int   c    = tid;
    const float bias = bh[c];
    const int   si   = tid & 127;
    const int   hh   = tid >> 7;          // row half for x staging
    const int   b0   = cid * 8;
    const size_t RS  = (size_t)NT * NI;

    __syncthreads();

    for (int it = 0; it < PC_TG / PC_Q; it++) {
        const int t0 = tg * PC_TG + it * PC_Q;

        // stage x for 4 tiles, transposed [q][k][8]
        #pragma unroll
        for (int q = 0; q < PC_Q; q++) {
            const float* xp = X + (size_t)(b0 + 4 * hh) * RS + (size_t)(t0 + q) * NI + si;
            float4 v;
            v.x = xp[0];
            v.y = xp[RS];
            v.z = xp[2 * RS];
            v.w = xp[3 * RS];
            *(float4*)(xT + q * 1024 + si * 8 + 4 * hh) = v;
        }
        __syncthreads();

        u64 acc[PC_Q][4];
        #pragma unroll
        for (int q = 0; q < PC_Q; q++) {
            u64 b2 = pack2(bias, bias);
            acc[q][0] = b2; acc[q][1] = b2; acc[q][2] = b2; acc[q][3] = b2;
        }

        #pragma unroll 4
        for (int k = 0; k < NI; k++) {
            float w = Wsp[k * NH + c];
            u64 wd = pack2(w, w);
            #pragma unroll
            for (int q = 0; q < PC_Q; q++) {
                ulonglong2 a0 = *(const ulonglong2*)(xT + q * 1024 + k * 8);
                ulonglong2 a1 = *(const ulonglong2*)(xT + q * 1024 + k * 8 + 4);
                fma2(acc[q][0], wd, a0.x); fma2(acc[q][1], wd, a0.y);
                fma2(acc[q][2], wd, a1.x); fma2(acc[q][3], wd, a1.y);
            }
        }

        // write U[q] tiles
        #pragma unroll
        for (int q = 0; q < PC_Q; q++) {
            size_t base = ((((size_t)(t0 + q) * 64 + cid) * 2 + (c >> 7)) * 128
                           + (c & 127)) * 8;
            float4 lo, hi;
            unpack2(acc[q][0], lo.x, lo.y); unpack2(acc[q][1], lo.z, lo.w);
            unpack2(acc[q][2], hi.x, hi.y); unpack2(acc[q][3], hi.z, hi.w);
            *(float4*)(g_U + base)     = lo;
            *(float4*)(g_U + base + 4) = hi;
        }
        __syncthreads();   // xT reused next iteration
    }
}

// ===========================================================================
// Kernel 2: persistent recurrence h(t+1) = tanh(U(t) + h(t)@Whh), fused proj.
// 64 clusters x 2 CTAs; cluster owns 8 batch rows; CTA rank owns 128 cols.
// 288 threads = 8 compute warps (k-split 32 each, 4 cols x 8 rows per lane)
//             + 1 loader warp (cp.async next U tile).
// ===========================================================================
constexpr int ROWS      = 8;
constexpr int CPC       = 128;
constexpr int R_THREADS = 288;
constexpr int HSTRIDE   = 12;                 // padded floats per hidden unit

// smem float offsets
constexpr int OFF_WS  = 0;                    // Whh slice [256][128]  32768
constexpr int OFF_PRE = 32768;                // partials [8][8][32][4] 8192
constexpr int OFF_HA  = OFF_PRE + 8192;       // h ping  [256][12]     3072
constexpr int OFF_HB  = OFF_HA + NH * HSTRIDE;// h pong                3072
constexpr int OFF_U0  = OFF_HB + NH * HSTRIDE;// U buf 0 [128][12]     1536
constexpr int OFF_U1  = OFF_U0 + CPC * HSTRIDE;
constexpr size_t R_SMEM = (size_t)(OFF_U1 + CPC * HSTRIDE) * 4;  // 200704 B

__global__ void __launch_bounds__(R_THREADS, 1) __cluster_dims__(2, 1, 1)
rnn_recur_kernel(const float* __restrict__ Whh,
                 const float* __restrict__ Whq,
                 const float* __restrict__ bq,
                 float* __restrict__ out)
{
    extern __shared__ float sm[];
    float* Ws  = sm + OFF_WS;
    float* pre = sm + OFF_PRE;
    float* hAp = sm + OFF_HA;
    float* hBp = sm + OFF_HB;
    float* Ub0 = sm + OFF_U0;
    float* Ub1 = sm + OFF_U1;

    cg::cluster_group cl = cg::this_cluster();
    const int rank  = (int)cl.block_rank();
    const int cid   = blockIdx.x >> 1;
    const int tid   = threadIdx.x;
    const int cb    = rank * CPC;
    const int bbase = cid * ROWS;

    // ---- stage Whh slice: Ws[k][j] = Whh[k][cb+j], float4 vectorized ----
    for (int i = tid; i < NH * CPC / 4; i += R_THREADS) {
        int k = i >> 5, j4 = (i & 31) * 4;
        ((float4*)Ws)[i] = *(const float4*)(Whh + (size_t)k * NH + cb + j4);
    }
    // zero h(0)
    for (int i = tid; i < NH * HSTRIDE; i += R_THREADS) hAp[i] = 0.0f;

    // U smem base addresses for cp.async
    const uint32_t u0_s = (uint32_t)__cvta_generic_to_shared(Ub0);
    const uint32_t u1_s = (uint32_t)__cvta_generic_to_shared(Ub1);

    // ---- preload U(0) into Ub0 (loader warp) ----
    if (tid >= 256) {
        const int lane = tid - 256;
        const float* src = g_U + ((size_t)(0 * 64 + cid) * 2 + rank) * 1024;
        #pragma unroll
        for (int i = 0; i < 8; i++) {
            int idx = i * 32 + lane;
            uint32_t d = u0_s + (uint32_t)((idx >> 1) * 48 + (idx & 1) * 16);
            cp16(d, src + idx * 4);
        }
        cp_commit();
        cp_wait0();
    }

    // roles
    const int wid = tid >> 5;          // 0..7 compute, 8 loader
    const int l   = tid & 31;
    const int fcol  = tid & 127;       // finalize column (tid<256)
    const int fhalf = (tid >> 7) & 1;  // finalize row-half

    float* hcur = hAp;
    float* hnxt = hBp;
    float* pA = (float*)cl.map_shared_rank(hAp, rank ^ 1);
    float* pB = (float*)cl.map_shared_rank(hBp, rank ^ 1);
    float* pnxt = pB;

    __syncthreads();
    cl.sync();

    for (int t = 0; t < NT; t++) {
        if (wid < 8) {
            // ---- compute partials: k in [32*wid, 32*wid+32), 4 cols x 8 rows ----
            const float* wp = Ws + (wid * 32) * CPC + 4 * l;
            const char*  hp = (const char*)hcur + (wid * 32) * (HSTRIDE * 4);

            u64 a00=0,a01=0,a02=0,a03=0, a10=0,a11=0,a12=0,a13=0;
            u64 a20=0,a21=0,a22=0,a23=0, a30=0,a31=0,a32=0,a33=0;

            #pragma unroll 8
            for (int k = 0; k < 32; k++) {
                float4 wv = *(const float4*)wp;  wp += CPC;
                u64 w0 = pack2(wv.x, wv.x);
                u64 w1 = pack2(wv.y, wv.y);
                u64 w2 = pack2(wv.z, wv.z);
                u64 w3 = pack2(wv.w, wv.w);
                ulonglong2 h01 = *(const ulonglong2*)hp;        // rows 0-3
                ulonglong2 h23 = *(const ulonglong2*)(hp + 16); // rows 4-7
                hp += HSTRIDE * 4;
                fma2(a00, w0, h01.x); fma2(a01, w0, h01.y);
                fma2(a02, w0, h23.x); fma2(a03, w0, h23.y);
                fma2(a10, w1, h01.x); fma2(a11, w1, h01.y);
                fma2(a12, w1, h23.x); fma2(a13, w1, h23.y);
                fma2(a20, w2, h01.x); fma2(a21, w2, h01.y);
                fma2(a22, w2, h23.x); fma2(a23, w2, h23.y);
                fma2(a30, w3, h01.x); fma2(a31, w3, h01.y);
                fma2(a32, w3, h23.x); fma2(a33, w3, h23.y);
            }

            // partial layout: pre[w][j][l][4], j = 2c + half
            float* pb = pre + wid * 1024 + l * 4;
            *(ulonglong2*)(pb + 0 * 128) = make_ulonglong2(a00, a01);
            *(ulonglong2*)(pb + 1 * 128) = make_ulonglong2(a02, a03);
            *(ulonglong2*)(pb + 2 * 128) = make_ulonglong2(a10, a11);
            *(ulonglong2*)(pb + 3 * 128) = make_ulonglong2(a12, a13);
            *(ulonglong2*)(pb + 4 * 128) = make_ulonglong2(a20, a21);
            *(ulonglong2*)(pb + 5 * 128) = make_ulonglong2(a22, a23);
            *(ulonglong2*)(pb + 6 * 128) = make_ulonglong2(a30, a31);
            *(ulonglong2*)(pb + 7 * 128) = make_ulonglong2(a32, a33);
        } else if (t + 1 < NT) {
            // ---- loader: U(t+1) -> other U buffer ----
            const int lane = tid - 256;
            const float* src = g_U + ((size_t)((t + 1) * 64 + cid) * 2 + rank) * 1024;
            const uint32_t db = ((t + 1) & 1) ? u1_s : u0_s;
            #pragma unroll
            for (int i = 0; i < 8; i++) {
                int idx = i * 32 + lane;
                uint32_t d = db + (uint32_t)((idx >> 1) * 48 + (idx & 1) * 16);
                cp16(d, src + idx * 4);
            }
            cp_commit();
            cp_wait0();
        }
        __syncthreads();

        if (tid < 256) {
            // ---- finalize: U + sum of 8 partials, tanh, publish own+peer ----
            const float* ub = (t & 1) ? Ub1 : Ub0;
            ulonglong2 s = *(const ulonglong2*)(ub + fcol * HSTRIDE + fhalf * 4);
            const float* pp = pre + (2 * (fcol & 3) + fhalf) * 128 + (fcol >> 2) * 4;
            #pragma unroll
            for (int w = 0; w < 8; w++) {
                ulonglong2 q = *(const ulonglong2*)(pp + w * 1024);
                fadd2(s.x, q.x);
                fadd2(s.y, q.y);
            }
            float r0, r1, r2, r3;
            unpack2(s.x, r0, r1);
            unpack2(s.y, r2, r3);
            float4 hv = make_float4(tanhf(r0), tanhf(r1), tanhf(r2), tanhf(r3));

            const int hoff = (cb + fcol) * HSTRIDE + fhalf * 4;
            *(float4*)(hnxt + hoff) = hv;
            *(float4*)(pnxt + hoff) = hv;
        }

        cl.sync();   // peer h visible; everyone done with hcur and pre

        float* tmp = hcur; hcur = hnxt; hnxt = tmp;
        pnxt = (hnxt == hAp) ? pA : pB;
    }

    // ---- fused projection: out[8 rows][NC]; rank covers 64 out columns ----
    if (tid < 256) {
        const int c  = tid & 63;
        const int rp = tid >> 6;            // row pair 0..3
        const int gc = rank * 64 + c;

        float acc0 = 0.0f, acc1 = 0.0f;
        const float* wq = Whq + gc;
        #pragma unroll 8
        for (int k = 0; k < NH; k++) {
            float2 hh = *(const float2*)(hcur + k * HSTRIDE + 2 * rp);
            float  wv = wq[(size_t)k * NC];
            acc0 = fmaf(hh.x, wv, acc0);
            acc1 = fmaf(hh.y, wv, acc1);
        }
        const float bqv = bq[gc];
        const int r0 = bbase + 2 * rp;
        out[(size_t)r0 * NC + gc]       = acc0 + bqv;
        out[(size_t)(r0 + 1) * NC + gc] = acc1 + bqv;
    }
}

extern "C" void kernel_launch(void* const* d_in, const int* in_sizes, int n_in,
                              void* d_out, int out_size)
{
    const float* X   = (const float*)d_in[0];
    const float* Wxh = (const float*)d_in[1];
    const float* Whh = (const float*)d_in[2];
    const float* bh  = (const float*)d_in[3];
    const float* Whq = (const float*)d_in[4];
    const float* bq  = (const float*)d_in[5];
    float* out = (float*)d_out;

    cudaFuncSetAttribute(precompute_kernel,
                         cudaFuncAttributeMaxDynamicSharedMemorySize, (int)PC_SMEM);
    cudaFuncSetAttribute(rnn_recur_kernel,
                         cudaFuncAttributeMaxDynamicSharedMemorySize, (int)R_SMEM);

    precompute_kernel<<<64 * 16, PC_THREADS, PC_SMEM>>>(X, Wxh, bh);
    rnn_recur_kernel<<<(NB / ROWS) * 2, R_THREADS, R_SMEM>>>(Whh, Whq, bq, out);
}

// round 6
// speedup vs baseline: 1.2757x; 1.0758x over previous
#include <cuda_runtime.h>
#include <cooperative_groups.h>

namespace cg = cooperative_groups;

// Problem shapes
#define NB 512
#define NT 512
#define NI 128
#define NH 256
#define NC 128

typedef unsigned long long u64;

// Precomputed input projection U = X@Wxh + bh:
//   U[t][cid][rank][col(128)][row(8)]  (256 MB static scratch)
__device__ float g_U[(size_t)NT * 64 * 2 * 128 * 8];

__device__ __forceinline__ u64 pack2(float a, float b) {
    u64 r; asm("mov.b64 %0, {%1, %2};" : "=l"(r) : "f"(a), "f"(b)); return r;
}
__device__ __forceinline__ void unpack2(u64 v, float& a, float& b) {
    asm("mov.b64 {%0, %1}, %2;" : "=f"(a), "=f"(b) : "l"(v));
}
__device__ __forceinline__ void fma2(u64& d, u64 a, u64 b) {
    asm("fma.rn.f32x2 %0, %1, %2, %0;" : "+l"(d) : "l"(a), "l"(b));
}
__device__ __forceinline__ void fadd2(u64& d, u64 a) {
    asm("add.rn.f32x2 %0, %0, %1;" : "+l"(d) : "l"(a));
}

// ===========================================================================
// Kernel 1: precompute U = X@Wxh + bh   (unchanged from round 5)
// ===========================================================================
constexpr int PC_THREADS = 256;
constexpr int PC_Q       = 4;
constexpr int PC_TG      = 32;
constexpr size_t PC_SMEM = (size_t)(NI * NH + PC_Q * NI * 8) * 4;

__global__ void __launch_bounds__(PC_THREADS, 1)
precompute_kernel(const float* __restrict__ X,
                  const float* __restrict__ Wxh,
                  const float* __restrict__ bh)
{
    extern __shared__ float smp[];
    float* Wsp = smp;
    float* xT  = smp + NI * NH;

    const int cid = blockIdx.x >> 4;
    const int tg  = blockIdx.x & 15;
    const int tid = threadIdx.x;

    for (int i = tid; i < NI * NH / 4; i += PC_THREADS)
        ((float4*)Wsp)[i] = ((const float4*)Wxh)[i];

    const int   c    = tid;
    const float bias = bh[c];
    const int   si   = tid & 127;
    const int   hh   = tid >> 7;
    const int   b0   = cid * 8;
    const size_t RS  = (size_t)NT * NI;

    __syncthreads();

    for (int it = 0; it < PC_TG / PC_Q; it++) {
        const int t0 = tg * PC_TG + it * PC_Q;

        #pragma unroll
        for (int q = 0; q < PC_Q; q++) {
            const float* xp = X + (size_t)(b0 + 4 * hh) * RS + (size_t)(t0 + q) * NI + si;
            float4 v;
            v.x = xp[0];
            v.y = xp[RS];
            v.z = xp[2 * RS];
            v.w = xp[3 * RS];
            *(float4*)(xT + q * 1024 + si * 8 + 4 * hh) = v;
        }
        __syncthreads();

        u64 acc[PC_Q][4];
        #pragma unroll
        for (int q = 0; q < PC_Q; q++) {
            u64 b2 = pack2(bias, bias);
            acc[q][0] = b2; acc[q][1] = b2; acc[q][2] = b2; acc[q][3] = b2;
        }

        #pragma unroll 4
        for (int k = 0; k < NI; k++) {
            float w = Wsp[k * NH + c];
            u64 wd = pack2(w, w);
            #pragma unroll
            for (int q = 0; q < PC_Q; q++) {
                ulonglong2 a0 = *(const ulonglong2*)(xT + q * 1024 + k * 8);
                ulonglong2 a1 = *(const ulonglong2*)(xT + q * 1024 + k * 8 + 4);
                fma2(acc[q][0], wd, a0.x); fma2(acc[q][1], wd, a0.y);
                fma2(acc[q][2], wd, a1.x); fma2(acc[q][3], wd, a1.y);
            }
        }

        #pragma unroll
        for (int q = 0; q < PC_Q; q++) {
            size_t base = ((((size_t)(t0 + q) * 64 + cid) * 2 + (c >> 7)) * 128
                           + (c & 127)) * 8;
            float4 lo, hi;
            unpack2(acc[q][0], lo.x, lo.y); unpack2(acc[q][1], lo.z, lo.w);
            unpack2(acc[q][2], hi.x, hi.y); unpack2(acc[q][3], hi.z, hi.w);
            *(float4*)(g_U + base)     = lo;
            *(float4*)(g_U + base + 4) = hi;
        }
        __syncthreads();
    }
}

// ===========================================================================
// Kernel 2: recurrence h(t+1)=tanh(U(t)+h(t)@Whh), weights in REGISTERS.
// 64 clusters x 2 CTAs; cluster = 8 batch rows; CTA rank = 128 cols.
// 288 threads: warps 0-7 compute (k-slice of 32 each; lane = 4 cols x 8 rows,
// Whh slice held in 128 registers), warp 8 loads next U tile (LDG+STS).
// Partials exchanged through smem with a lane-rotated, conflict-free layout.
// ===========================================================================
constexpr int R_THREADS = 288;

// smem float offsets
constexpr int OFF_PRE = 0;                      // [8 warps][32 lanes][8 slots][4] = 8192
constexpr int OFF_HA  = 8192;                   // h ping  [256 col][8 rows] = 2048
constexpr int OFF_HB  = OFF_HA + NH * 8;        // h pong
constexpr int OFF_U0  = OFF_HB + NH * 8;        // U buf0 [128 col][8 rows] = 1024
constexpr int OFF_U1  = OFF_U0 + 128 * 8;       // U buf1
constexpr size_t R_SMEM = (size_t)(OFF_U1 + 128 * 8) * 4;   // 57344 B

__global__ void __launch_bounds__(R_THREADS, 1) __cluster_dims__(2, 1, 1)
rnn_recur_kernel(const float* __restrict__ Whh,
                 const float* __restrict__ Whq,
                 const float* __restrict__ bq,
                 float* __restrict__ out)
{
    extern __shared__ float sm[];
    float* pre = sm + OFF_PRE;

    cg::cluster_group cl = cg::this_cluster();
    const int rank  = (int)cl.block_rank();
    const int cid   = blockIdx.x >> 1;
    const int tid   = threadIdx.x;
    const int cb    = rank * 128;
    const int bbase = cid * 8;

    const int wid = tid >> 5;
    const int l   = tid & 31;

    // ---- weights into registers: lane = cols cb+4l..+4, k-slice wid*32..+32 ----
    ulonglong2 wv[32];
    if (wid < 8) {
        const float* wp = Whh + (size_t)(wid * 32) * NH + cb + 4 * l;
        #pragma unroll
        for (int k = 0; k < 32; k++)
            wv[k] = *(const ulonglong2*)(wp + (size_t)k * NH);
    }

    // ---- zero h(0) ----
    for (int i = tid; i < NH * 8; i += R_THREADS) sm[OFF_HA + i] = 0.0f;

    // ---- loader preload U(0) ----
    if (wid == 8) {
        const float* s0 = g_U + ((size_t)(0 * 64 + cid) * 2 + rank) * 1024;
        #pragma unroll
        for (int i = 0; i < 8; i++)
            *(float4*)(sm + OFF_U0 + (i * 32 + l) * 4) = *(const float4*)(s0 + (i * 32 + l) * 4);
    }

    // ---- finalize constants: thread -> (col fc, row-half fh) ----
    const int fc    = tid >> 1;
    const int fh    = tid & 1;
    const int flo   = fc >> 2;                       // owning lane in each warp
    const int fslot = (((fc & 3) * 2 + fh) + flo) & 7;   // rotated slot

    float* hb0 = sm + OFF_HA;
    float* hb1 = sm + OFF_HB;
    float* pb0 = (float*)cl.map_shared_rank(hb0, rank ^ 1);
    float* pb1 = (float*)cl.map_shared_rank(hb1, rank ^ 1);

    __syncthreads();
    cl.sync();

    for (int t = 0; t < NT; t++) {
        float* hcur = (t & 1) ? hb1 : hb0;

        if (wid < 8) {
            // ---- compute: acc[c][rpair] over k-slice, 4 cols x 8 rows ----
            const float* hp = hcur + (wid * 32) * 8;
            u64 acc[4][4];
            #pragma unroll
            for (int c = 0; c < 4; c++)
                #pragma unroll
                for (int r = 0; r < 4; r++) acc[c][r] = 0ull;

            #pragma unroll
            for (int k = 0; k < 32; k++) {
                ulonglong2 hlo = *(const ulonglong2*)(hp + k * 8);      // rows 0-3
                ulonglong2 hhi = *(const ulonglong2*)(hp + k * 8 + 4);  // rows 4-7
                float w0, w1, w2, w3;
                unpack2(wv[k].x, w0, w1);
                unpack2(wv[k].y, w2, w3);
                u64 d0 = pack2(w0, w0), d1 = pack2(w1, w1);
                u64 d2 = pack2(w2, w2), d3 = pack2(w3, w3);
                fma2(acc[0][0], d0, hlo.x); fma2(acc[0][1], d0, hlo.y);
                fma2(acc[0][2], d0, hhi.x); fma2(acc[0][3], d0, hhi.y);
                fma2(acc[1][0], d1, hlo.x); fma2(acc[1][1], d1, hlo.y);
                fma2(acc[1][2], d1, hhi.x); fma2(acc[1][3], d1, hhi.y);
                fma2(acc[2][0], d2, hlo.x); fma2(acc[2][1], d2, hlo.y);
                fma2(acc[2][2], d2, hhi.x); fma2(acc[2][3], d2, hhi.y);
                fma2(acc[3][0], d3, hlo.x); fma2(acc[3][1], d3, hlo.y);
                fma2(acc[3][2], d3, hhi.x); fma2(acc[3][3], d3, hhi.y);
            }

            // ---- store partials, lane-rotated slots (conflict-free) ----
            float* pb = pre + wid * 1024 + l * 32;
            #pragma unroll
            for (int c = 0; c < 4; c++) {
                #pragma unroll
                for (int h2 = 0; h2 < 2; h2++) {
                    int slot = ((c * 2 + h2) + l) & 7;
                    ulonglong2 v;
                    v.x = acc[c][2 * h2];
                    v.y = acc[c][2 * h2 + 1];
                    *(ulonglong2*)(pb + slot * 4) = v;
                }
            }
        } else {
            // ---- loader: U(t+1) global -> smem buffer (t+1)&1 ----
            if (t + 1 < NT) {
                const float* sg = g_U + ((size_t)((t + 1) * 64 + cid) * 2 + rank) * 1024;
                float* ub = sm + (((t + 1) & 1) ? OFF_U1 : OFF_U0);
                float4 v[8];
                #pragma unroll
                for (int i = 0; i < 8; i++) v[i] = *(const float4*)(sg + (i * 32 + l) * 4);
                #pragma unroll
                for (int i = 0; i < 8; i++) *(float4*)(ub + (i * 32 + l) * 4) = v[i];
            }
        }
        __syncthreads();

        if (tid < 256) {
            // ---- finalize: U + sum of 8 warp partials, tanh, publish ----
            const float* uc = sm + ((t & 1) ? OFF_U1 : OFF_U0);
            ulonglong2 s = *(const ulonglong2*)(uc + fc * 8 + fh * 4);
            const float* pp = pre + flo * 32 + fslot * 4;
            #pragma unroll
            for (int w = 0; w < 8; w++) {
                ulonglong2 q = *(const ulonglong2*)(pp + w * 1024);
                fadd2(s.x, q.x);
                fadd2(s.y, q.y);
            }
            float r0, r1, r2, r3;
            unpack2(s.x, r0, r1);
            unpack2(s.y, r2, r3);
            float4 hv = make_float4(tanhf(r0), tanhf(r1), tanhf(r2), tanhf(r3));

            const int hoff = (cb + fc) * 8 + fh * 4;
            float* hn = ((t & 1) ? hb0 : hb1) + hoff;
            float* pn = ((t & 1) ? pb0 : pb1) + hoff;
            *(float4*)hn = hv;
            *(float4*)pn = hv;
        }

        cl.sync();   // peer h visible; everyone done with hcur / U buffer
    }

    // ---- fused projection: rank covers 64 out columns, 8 rows ----
    const float* hf = (NT & 1) ? hb1 : hb0;
    if (tid < 256) {
        const int c  = tid & 63;
        const int rp = tid >> 6;            // row pair 0..3
        const int gc = rank * 64 + c;

        float acc0 = 0.0f, acc1 = 0.0f;
        const float* wq = Whq + gc;
        #pragma unroll 8
        for (int k = 0; k < NH; k++) {
            float2 hh = *(const float2*)(hf + k * 8 + 2 * rp);
            float  wv2 = wq[(size_t)k * NC];
            acc0 = fmaf(hh.x, wv2, acc0);
            acc1 = fmaf(hh.y, wv2, acc1);
        }
        const float bqv = bq[gc];
        const int r0 = bbase + 2 * rp;
        out[(size_t)r0 * NC + gc]       = acc0 + bqv;
        out[(size_t)(r0 + 1) * NC + gc] = acc1 + bqv;
    }
}

extern "C" void kernel_launch(void* const* d_in, const int* in_sizes, int n_in,
                              void* d_out, int out_size)
{
    const float* X   = (const float*)d_in[0];
    const float* Wxh = (const float*)d_in[1];
    const float* Whh = (const float*)d_in[2];
    const float* bh  = (const float*)d_in[3];
    const float* Whq = (const float*)d_in[4];
    const float* bq  = (const float*)d_in[5];
    float* out = (float*)d_out;

    cudaFuncSetAttribute(precompute_kernel,
                         cudaFuncAttributeMaxDynamicSharedMemorySize, (int)PC_SMEM);
    cudaFuncSetAttribute(rnn_recur_kernel,
                         cudaFuncAttributeMaxDynamicSharedMemorySize, (int)R_SMEM);

    precompute_kernel<<<64 * 16, PC_THREADS, PC_SMEM>>>(X, Wxh, bh);
    rnn_recur_kernel<<<(NB / 8) * 2, R_THREADS, R_SMEM>>>(Whh, Whq, bq, out);
}